// round 10
// baseline (speedup 1.0000x reference)
#include <cuda_runtime.h>

// ---------------------------------------------------------------------------
// SSIM loss, fused strip kernel (rolling horizontal-blur buffer),
// float4 global loads, stage-B packed f32x2 math on pre-packed H planes.
// Block owns a 64 (x) x 128 (y) strip, processed as 8 chunks of 16 rows.
// Raw buffer covers gx in [tx0-8, tx0+72): 80 cols, aligned float4 LDG;
// interior blocks skip x-bounds checks (uniform branch).
// H layout (packed):  Hab = float2(mu1h, mu2h) plane [26][64]
//                     Hsq = float2(q1h, q2h)  plane [26][64]
//                     Hx  = float  (abh)      plane [26][64]
// Stage A: horizontal blur, scalar FFMA-imm accumulation, packed stores.
// Stage B: vertical blur; 14-tap register window per field, t-outer loop,
//          one weight-pair ULDC per t, fma.rn.f32x2 (2 FMA/slot) for the
//          4 packed fields + scalar FFMA-imm for ab.  4 ssim fractions
//          combine rationally -> ONE __fdividef per chunk.
// Reduce: warp shuffle -> block -> atomicAdd(double); counter-elected last
//         block writes 1 - mean and resets accumulators (replay-safe).
// ---------------------------------------------------------------------------

#define NTHREADS 256
#define TX 64
#define TY 16            // rows per chunk
#define NCHUNK 8         // chunks per strip
#define SY (TY * NCHUNK) // 128 rows per strip
#define RROWS 26         // TY + 10
#define RSTRIDE 80       // raw cols: gx in [tx0-8, tx0+72), float4-aligned
#define IMG 1024
#define NBLOCKS (16 * 8 * 32)

// float-offset layout
#define RAWF   (2 * RROWS * RSTRIDE)     // 4160 floats of raw tiles
#define PLANEF (RROWS * TX * 2)          // 3328 floats per packed plane
#define HABF   RAWF
#define HSQF   (HABF + PLANEF)
#define HXF    (HSQF + PLANEF)
#define WSUMF  (HXF + RROWS * TX)
#define SMEM_FLOATS (WSUMF + 8)
#define SMEM_BYTES (SMEM_FLOATS * 4)     // 49,952 B -> 4 blocks/SM

typedef unsigned long long ull;

#define W0 0.00102838f
#define W1 0.00759875f
#define W2 0.03600077f
#define W3 0.10936069f
#define W4 0.21300553f
#define W5 0.26601172f

static __device__ __forceinline__ float Wt(int t) {
    constexpr float w[11] = {W0, W1, W2, W3, W4, W5, W4, W3, W2, W1, W0};
    return w[t];
}

__constant__ float2 WB[11] = {
    {W0, W0}, {W1, W1}, {W2, W2}, {W3, W3}, {W4, W4}, {W5, W5},
    {W4, W4}, {W3, W3}, {W2, W2}, {W1, W1}, {W0, W0}};

static __device__ __forceinline__ void unpackf2(float& x, float& y, ull v) {
    asm("mov.b64 {%0, %1}, %2;" : "=f"(x), "=f"(y) : "l"(v));
}
static __device__ __forceinline__ ull f2fma(ull a, ull b, ull c) {
    ull r; asm("fma.rn.f32x2 %0, %1, %2, %3;"
               : "=l"(r) : "l"(a), "l"(b), "l"(c));
    return r;
}

__device__ double g_acc = 0.0;
__device__ unsigned g_count = 0u;

__global__ __launch_bounds__(NTHREADS, 4)
void ssim_main(const float* __restrict__ img1, const float* __restrict__ img2,
               float* __restrict__ out) {
    extern __shared__ float smem[];
    float* r1   = smem;                                // [RROWS][RSTRIDE]
    float* r2   = smem + RROWS * RSTRIDE;              // [RROWS][RSTRIDE]
    ull*   Hab  = reinterpret_cast<ull*>(smem + HABF); // [RROWS][TX] float2
    ull*   Hsq  = reinterpret_cast<ull*>(smem + HSQF); // [RROWS][TX] float2
    float* Hx   = smem + HXF;                          // [RROWS][TX]
    float* wsum = smem + WSUMF;                        // [8]

    const float C1f = 0.0004f;   // (0.01*2)^2
    const float C2f = 0.0036f;   // (0.03*2)^2

    const int tid = threadIdx.x;
    const int tx0 = blockIdx.x * TX;
    const int sy0 = blockIdx.y * SY;
    const size_t base = (size_t)blockIdx.z * (size_t)(IMG * IMG);
    const bool xedge = (blockIdx.x == 0) | (blockIdx.x == (IMG / TX - 1));

    float lsum = 0.f;

    #pragma unroll 1
    for (int ch = 0; ch < NCHUNK; ch++) {
        const int y0c = sy0 + ch * TY;   // first output row of this chunk

        if (ch == 0) {
            // ---- full raw load: rows 0..25 <-> gy in [y0c-5, y0c+21) -----
            if (!xedge) {
                for (int idx = tid; idx < RROWS * 20; idx += NTHREADS) {
                    const int r = idx / 20;
                    const int q = idx - r * 20;
                    const int gy = y0c + r - 5;
                    float4 a = make_float4(0.f, 0.f, 0.f, 0.f), b = a;
                    if ((unsigned)gy < (unsigned)IMG) {
                        const size_t o = base + (size_t)gy * IMG + (tx0 - 8 + 4 * q);
                        a = *reinterpret_cast<const float4*>(img1 + o);
                        b = *reinterpret_cast<const float4*>(img2 + o);
                    }
                    *reinterpret_cast<float4*>(r1 + r * RSTRIDE + 4 * q) = a;
                    *reinterpret_cast<float4*>(r2 + r * RSTRIDE + 4 * q) = b;
                }
            } else {
                for (int idx = tid; idx < RROWS * RSTRIDE; idx += NTHREADS) {
                    const int r = idx / RSTRIDE;
                    const int c = idx - r * RSTRIDE;
                    const int gy = y0c + r - 5;
                    const int gx = tx0 - 8 + c;
                    float a = 0.f, b = 0.f;
                    if ((unsigned)gy < (unsigned)IMG && (unsigned)gx < (unsigned)IMG) {
                        const size_t o = base + (size_t)gy * IMG + (size_t)gx;
                        a = __ldg(img1 + o);
                        b = __ldg(img2 + o);
                    }
                    r1[r * RSTRIDE + c] = a;
                    r2[r * RSTRIDE + c] = b;
                }
            }
            __syncthreads();

            // ---- stage A, all 26 rows, 8-col runs: 208 jobs --------------
            if (tid < RROWS * 8) {
                const int r  = tid >> 3;
                const int c0 = (tid & 7) * 8;
                const float4* p1 = reinterpret_cast<const float4*>(r1 + r * RSTRIDE + c0);
                const float4* p2 = reinterpret_cast<const float4*>(r2 + r * RSTRIDE + c0);

                float acc[5][8];
                #pragma unroll
                for (int f = 0; f < 5; f++)
                    #pragma unroll
                    for (int i = 0; i < 8; i++) acc[f][i] = 0.f;

                #pragma unroll
                for (int q = 0; q < 6; q++) {
                    const float4 v1 = p1[q];
                    const float4 v2 = p2[q];
                    const float a4[4] = {v1.x, v1.y, v1.z, v1.w};
                    const float b4[4] = {v2.x, v2.y, v2.z, v2.w};
                    #pragma unroll
                    for (int i = 0; i < 4; i++) {
                        const int k = 4 * q + i - 3;   // tap window index
                        if (k >= 0 && k < 18) {
                            const float a = a4[i];
                            const float b = b4[i];
                            const float aa = a * a;
                            const float bb = b * b;
                            const float ab = a * b;
                            #pragma unroll
                            for (int jj = 0; jj < 8; jj++) {
                                const int t = k - jj;
                                if (t >= 0 && t <= 10) {
                                    const float w = Wt(t);
                                    acc[0][jj] += w * a;
                                    acc[1][jj] += w * b;
                                    acc[2][jj] += w * aa;
                                    acc[3][jj] += w * bb;
                                    acc[4][jj] += w * ab;
                                }
                            }
                        }
                    }
                }
                // packed stores: Hab/Hsq as float2 pairs, Hx scalar plane
                float4* habp = reinterpret_cast<float4*>(Hab + r * TX + c0);
                float4* hsqp = reinterpret_cast<float4*>(Hsq + r * TX + c0);
                #pragma unroll
                for (int i = 0; i < 4; i++) {
                    habp[i] = make_float4(acc[0][2*i], acc[1][2*i],
                                          acc[0][2*i+1], acc[1][2*i+1]);
                    hsqp[i] = make_float4(acc[2][2*i], acc[3][2*i],
                                          acc[2][2*i+1], acc[3][2*i+1]);
                }
                float* hxp = Hx + r * TX + c0;
                *reinterpret_cast<float4*>(hxp) =
                    make_float4(acc[4][0], acc[4][1], acc[4][2], acc[4][3]);
                *reinterpret_cast<float4*>(hxp + 4) =
                    make_float4(acc[4][4], acc[4][5], acc[4][6], acc[4][7]);
            }
            __syncthreads();
        } else {
            __syncthreads();   // prev stage B must finish before H/raw reuse

            // ---- copy H rows 16..25 -> 0..9 (10-row overlap) -------------
            // Hab: 320 f4 jobs, Hsq: 320, Hx: 160 -> 800 total.
            for (int idx = tid; idx < 800; idx += NTHREADS) {
                if (idx < 640) {
                    const int p   = idx / 320;          // 0=Hab, 1=Hsq
                    const int rem = idx - p * 320;
                    const int r   = rem >> 5;           // 0..9
                    const int c4  = (rem & 31) * 4;     // 0..124 (floats)
                    const float* src = smem + HABF + p * PLANEF
                                     + (16 + r) * (TX * 2) + c4;
                    float* dst = smem + HABF + p * PLANEF + r * (TX * 2) + c4;
                    *reinterpret_cast<float4*>(dst) =
                        *reinterpret_cast<const float4*>(src);
                } else {
                    const int rem = idx - 640;          // 0..159
                    const int r   = rem >> 4;
                    const int c4  = (rem & 15) * 4;
                    *reinterpret_cast<float4*>(Hx + r * TX + c4) =
                        *reinterpret_cast<const float4*>(Hx + (16 + r) * TX + c4);
                }
            }

            // ---- load 16 new raw rows into rows 10..25 -------------------
            if (!xedge) {
                for (int idx = tid; idx < TY * 20; idx += NTHREADS) {
                    const int r = idx / 20;
                    const int q = idx - r * 20;
                    const int gy = y0c + 5 + r;
                    float4 a = make_float4(0.f, 0.f, 0.f, 0.f), b = a;
                    if ((unsigned)gy < (unsigned)IMG) {
                        const size_t o = base + (size_t)gy * IMG + (tx0 - 8 + 4 * q);
                        a = *reinterpret_cast<const float4*>(img1 + o);
                        b = *reinterpret_cast<const float4*>(img2 + o);
                    }
                    *reinterpret_cast<float4*>(r1 + (10 + r) * RSTRIDE + 4 * q) = a;
                    *reinterpret_cast<float4*>(r2 + (10 + r) * RSTRIDE + 4 * q) = b;
                }
            } else {
                for (int idx = tid; idx < TY * RSTRIDE; idx += NTHREADS) {
                    const int r = idx / RSTRIDE;
                    const int c = idx - r * RSTRIDE;
                    const int gy = y0c + 5 + r;
                    const int gx = tx0 - 8 + c;
                    float a = 0.f, b = 0.f;
                    if ((unsigned)gy < (unsigned)IMG && (unsigned)gx < (unsigned)IMG) {
                        const size_t o = base + (size_t)gy * IMG + (size_t)gx;
                        a = __ldg(img1 + o);
                        b = __ldg(img2 + o);
                    }
                    r1[(10 + r) * RSTRIDE + c] = a;
                    r2[(10 + r) * RSTRIDE + c] = b;
                }
            }
            __syncthreads();

            // ---- stage A, 16 new rows, 4-col runs: 256 jobs --------------
            {
                const int r  = 10 + (tid >> 4);       // H/raw row 10..25
                const int c0 = (tid & 15) * 4;
                const float4* p1 = reinterpret_cast<const float4*>(r1 + r * RSTRIDE + c0);
                const float4* p2 = reinterpret_cast<const float4*>(r2 + r * RSTRIDE + c0);

                float acc[5][4];
                #pragma unroll
                for (int f = 0; f < 5; f++)
                    #pragma unroll
                    for (int i = 0; i < 4; i++) acc[f][i] = 0.f;

                #pragma unroll
                for (int q = 0; q < 5; q++) {
                    const float4 v1 = p1[q];
                    const float4 v2 = p2[q];
                    const float a4[4] = {v1.x, v1.y, v1.z, v1.w};
                    const float b4[4] = {v2.x, v2.y, v2.z, v2.w};
                    #pragma unroll
                    for (int i = 0; i < 4; i++) {
                        const int k = 4 * q + i - 3;   // tap window index
                        if (k >= 0 && k < 14) {
                            const float a = a4[i];
                            const float b = b4[i];
                            const float aa = a * a;
                            const float bb = b * b;
                            const float ab = a * b;
                            #pragma unroll
                            for (int jj = 0; jj < 4; jj++) {
                                const int t = k - jj;
                                if (t >= 0 && t <= 10) {
                                    const float w = Wt(t);
                                    acc[0][jj] += w * a;
                                    acc[1][jj] += w * b;
                                    acc[2][jj] += w * aa;
                                    acc[3][jj] += w * bb;
                                    acc[4][jj] += w * ab;
                                }
                            }
                        }
                    }
                }
                float4* habp = reinterpret_cast<float4*>(Hab + r * TX + c0);
                float4* hsqp = reinterpret_cast<float4*>(Hsq + r * TX + c0);
                #pragma unroll
                for (int i = 0; i < 2; i++) {
                    habp[i] = make_float4(acc[0][2*i], acc[1][2*i],
                                          acc[0][2*i+1], acc[1][2*i+1]);
                    hsqp[i] = make_float4(acc[2][2*i], acc[3][2*i],
                                          acc[2][2*i+1], acc[3][2*i+1]);
                }
                *reinterpret_cast<float4*>(Hx + r * TX + c0) =
                    make_float4(acc[4][0], acc[4][1], acc[4][2], acc[4][3]);
            }
            __syncthreads();
        }

        // -------- Stage B: vertical blur + ssim, 4 rows per thread ---------
        // Packed f32x2 on Hab/Hsq, scalar FFMA-imm on Hx; t-outer loops with
        // one weight-pair ULDC per t.
        {
            const int c  = tid & (TX - 1);        // output column 0..63
            const int g4 = (tid >> 6) * 4;        // first output row in chunk
            ull win[14];

            // field pass 1: (mu1, mu2)
            const ull* habc = Hab + g4 * TX + c;
            #pragma unroll
            for (int k = 0; k < 14; k++) win[k] = habc[k * TX];
            ull a01[4] = {0ull, 0ull, 0ull, 0ull};
            #pragma unroll
            for (int t = 0; t < 11; t++) {
                const ull w2 = *reinterpret_cast<const ull*>(&WB[t]);
                #pragma unroll
                for (int jj = 0; jj < 4; jj++)
                    a01[jj] = f2fma(w2, win[jj + t], a01[jj]);
            }

            // field pass 2: (q1, q2)
            const ull* hsqc = Hsq + g4 * TX + c;
            #pragma unroll
            for (int k = 0; k < 14; k++) win[k] = hsqc[k * TX];
            ull a23[4] = {0ull, 0ull, 0ull, 0ull};
            #pragma unroll
            for (int t = 0; t < 11; t++) {
                const ull w2 = *reinterpret_cast<const ull*>(&WB[t]);
                #pragma unroll
                for (int jj = 0; jj < 4; jj++)
                    a23[jj] = f2fma(w2, win[jj + t], a23[jj]);
            }

            // field pass 3: ab (scalar, FFMA-imm)
            float winx[14];
            const float* hxc = Hx + g4 * TX + c;
            #pragma unroll
            for (int k = 0; k < 14; k++) winx[k] = hxc[k * TX];
            float a4[4] = {0.f, 0.f, 0.f, 0.f};
            #pragma unroll
            for (int t = 0; t < 11; t++) {
                const float w = Wt(t);
                #pragma unroll
                for (int jj = 0; jj < 4; jj++)
                    a4[jj] += w * winx[jj + t];
            }

            // ssim fractions; combine 4 rationally -> ONE divide per chunk.
            float Nn[4], Dd[4];
            #pragma unroll
            for (int jj = 0; jj < 4; jj++) {
                float mu1, mu2, q1, q2;
                unpackf2(mu1, mu2, a01[jj]);
                unpackf2(q1,  q2,  a23[jj]);
                const float mu12 = mu1 * mu2;
                const float mu1s = mu1 * mu1;
                const float mu2s = mu2 * mu2;
                const float s1  = q1 - mu1s;
                const float s2  = q2 - mu2s;
                const float s12 = a4[jj] - mu12;
                Nn[jj] = (2.f * mu12 + C1f) * (2.f * s12 + C2f);
                Dd[jj] = (mu1s + mu2s + C1f) * (s1 + s2 + C2f);
            }
            const float n01 = Nn[0] * Dd[1] + Nn[1] * Dd[0];
            const float d01 = Dd[0] * Dd[1];
            const float n23 = Nn[2] * Dd[3] + Nn[3] * Dd[2];
            const float d23 = Dd[2] * Dd[3];
            lsum += __fdividef(n01 * d23 + n23 * d01, d01 * d23);
        }
    }

    // -------- Reduction ----------------------------------------------------
    #pragma unroll
    for (int o = 16; o > 0; o >>= 1)
        lsum += __shfl_xor_sync(0xffffffffu, lsum, o);
    if ((tid & 31) == 0) wsum[tid >> 5] = lsum;
    __syncthreads();
    if (tid == 0) {
        float bs = 0.f;
        #pragma unroll
        for (int w = 0; w < 8; w++) bs += wsum[w];
        atomicAdd(&g_acc, (double)bs);
        __threadfence();
        const unsigned old = atomicAdd(&g_count, 1u);
        if (old == NBLOCKS - 1) {
            const double s = *((volatile double*)&g_acc);
            out[0] = (float)(1.0 - s * (1.0 / 33554432.0));  // 32*1024*1024
            *((volatile double*)&g_acc) = 0.0;
            __threadfence();
            atomicExch(&g_count, 0u);
        }
    }
}

extern "C" void kernel_launch(void* const* d_in, const int* in_sizes, int n_in,
                              void* d_out, int out_size) {
    (void)in_sizes; (void)n_in; (void)out_size;
    const float* img1 = (const float*)d_in[0];
    const float* img2 = (const float*)d_in[1];
    float* out = (float*)d_out;

    static int smem_set = 0;
    if (!smem_set) {
        cudaFuncSetAttribute(ssim_main,
                             cudaFuncAttributeMaxDynamicSharedMemorySize,
                             SMEM_BYTES);
        smem_set = 1;
    }

    dim3 grid(IMG / TX, IMG / SY, 32);   // 16 x 8 x 32 = 4096 blocks
    ssim_main<<<grid, NTHREADS, SMEM_BYTES>>>(img1, img2, out);
}

// round 11
// speedup vs baseline: 1.1525x; 1.1525x over previous
#include <cuda_runtime.h>

// ---------------------------------------------------------------------------
// SSIM loss, fused strip kernel, ring-buffered horizontal-blur planes,
// gmem-direct stage A (no raw smem tile), 5 blocks/SM target.
// Block owns a 64 (x) x 128 (y) strip, processed as 8 chunks of 16 rows.
// H: 5 scalar planes [32][68] used as a 32-row ring keyed by (gy & 31) —
//    no copy-down, no stage-0 loader, 2 barriers per chunk.
// Stage A: horizontal 11-tap blur of 5 moment fields, 4-col register runs,
//          inputs read directly from gmem as aligned float4 (interior
//          blocks; 2/16 x-edge blocks take a predicated scalar path).
// Stage B: vertical 11-tap blur + ssim epilogue, 4-row runs; 4 fractions
//          combine rationally -> ONE __fdividef per chunk.
// Weights are compile-time immediates -> FFMA-imm (rt_SMSP=1).
// Reduce: warp shuffle -> block -> atomicAdd(double); counter-elected last
//         block writes 1 - mean and resets accumulators (replay-safe).
// ---------------------------------------------------------------------------

#define NTHREADS 256
#define TX 64
#define TY 16            // rows per chunk
#define NCHUNK 8         // chunks per strip
#define SY (TY * NCHUNK) // 128 rows per strip
#define HROWS 32         // ring rows (power of 2)
#define HSTRIDE 68       // H row stride (floats), multiple of 4
#define IMG 1024
#define NBLOCKS (16 * 8 * 32)

#define PLANEF (HROWS * HSTRIDE)
#define SMEM_FLOATS (5 * PLANEF + 8)
#define SMEM_BYTES (SMEM_FLOATS * 4)     // 43,552 B -> 5 blocks/SM

static __device__ __forceinline__ float Wt(int t) {
    // Gaussian, WIN=11, SIGMA=1.5, normalized; compile-time constants so
    // ptxas emits FFMA-imm (rt_SMSP=1, 2x tput vs 3-reg FFMA).
    constexpr float w[6] = {0.00102838f, 0.00759875f, 0.03600077f,
                            0.10936069f, 0.21300553f, 0.26601172f};
    return (t < 6) ? w[t] : w[10 - t];
}

__device__ double g_acc = 0.0;
__device__ unsigned g_count = 0u;

__global__ __launch_bounds__(NTHREADS, 5)
void ssim_main(const float* __restrict__ img1, const float* __restrict__ img2,
               float* __restrict__ out) {
    extern __shared__ float smem[];
    float* H    = smem;                 // [5][HROWS][HSTRIDE] ring
    float* wsum = smem + 5 * PLANEF;    // [8]

    const float C1f = 0.0004f;   // (0.01*2)^2
    const float C2f = 0.0036f;   // (0.03*2)^2

    const int tid = threadIdx.x;
    const int tx0 = blockIdx.x * TX;
    const int sy0 = blockIdx.y * SY;
    const size_t base = (size_t)blockIdx.z * (size_t)(IMG * IMG);
    const bool xedge = (blockIdx.x == 0) | (blockIdx.x == (IMG / TX - 1));

    float lsum = 0.f;

    #pragma unroll 1
    for (int ch = 0; ch < NCHUNK; ch++) {
        const int y0c = sy0 + ch * TY;   // first output row of this chunk

        if (ch > 0) __syncthreads();     // stage B readers done before slot reuse

        // -------- Stage A: horizontal blur of new rows into ring ------------
        // chunk 0: 26 rows (gy in [y0c-5, y0c+21)), 416 jobs (2 passes);
        // steady : 16 rows (gy in [y0c+5, y0c+21)), 256 jobs (1 pass).
        const int nrows  = (ch == 0) ? 26 : TY;
        const int row_lo = (ch == 0) ? -5 : 5;
        for (int j = tid; j < nrows * 16; j += NTHREADS) {
            const int r  = j >> 4;
            const int c0 = (j & 15) * 4;            // output cols c0..c0+3
            const int gy = y0c + row_lo + r;
            const int slot = gy & (HROWS - 1);

            float acc[5][4];
            #pragma unroll
            for (int f = 0; f < 5; f++)
                #pragma unroll
                for (int i = 0; i < 4; i++) acc[f][i] = 0.f;

            if ((unsigned)gy < (unsigned)IMG) {
                const size_t rowo = base + (size_t)gy * IMG;
                const int gx0 = tx0 - 8 + c0;       // window start (aligned 4)
                if (!xedge) {
                    #pragma unroll
                    for (int q = 0; q < 5; q++) {
                        const float4 v1 = *reinterpret_cast<const float4*>(
                            img1 + rowo + gx0 + 4 * q);
                        const float4 v2 = *reinterpret_cast<const float4*>(
                            img2 + rowo + gx0 + 4 * q);
                        const float a4[4] = {v1.x, v1.y, v1.z, v1.w};
                        const float b4[4] = {v2.x, v2.y, v2.z, v2.w};
                        #pragma unroll
                        for (int i = 0; i < 4; i++) {
                            const int k = 4 * q + i - 3;   // tap window index
                            if (k >= 0 && k < 14) {
                                const float a = a4[i];
                                const float b = b4[i];
                                const float aa = a * a;
                                const float bb = b * b;
                                const float ab = a * b;
                                #pragma unroll
                                for (int jj = 0; jj < 4; jj++) {
                                    const int t = k - jj;
                                    if (t >= 0 && t <= 10) {
                                        const float w = Wt(t);
                                        acc[0][jj] += w * a;
                                        acc[1][jj] += w * b;
                                        acc[2][jj] += w * aa;
                                        acc[3][jj] += w * bb;
                                        acc[4][jj] += w * ab;
                                    }
                                }
                            }
                        }
                    }
                } else {
                    // edge blocks: predicated scalar loads (2/16 of grid.x)
                    #pragma unroll
                    for (int q = 0; q < 5; q++) {
                        #pragma unroll
                        for (int i = 0; i < 4; i++) {
                            const int k = 4 * q + i - 3;
                            if (k >= 0 && k < 14) {
                                const int gx = gx0 + 4 * q + i;
                                float a = 0.f, b = 0.f;
                                if ((unsigned)gx < (unsigned)IMG) {
                                    a = __ldg(img1 + rowo + gx);
                                    b = __ldg(img2 + rowo + gx);
                                }
                                const float aa = a * a;
                                const float bb = b * b;
                                const float ab = a * b;
                                #pragma unroll
                                for (int jj = 0; jj < 4; jj++) {
                                    const int t = k - jj;
                                    if (t >= 0 && t <= 10) {
                                        const float w = Wt(t);
                                        acc[0][jj] += w * a;
                                        acc[1][jj] += w * b;
                                        acc[2][jj] += w * aa;
                                        acc[3][jj] += w * bb;
                                        acc[4][jj] += w * ab;
                                    }
                                }
                            }
                        }
                    }
                }
            }
            #pragma unroll
            for (int f = 0; f < 5; f++) {
                *reinterpret_cast<float4*>(
                    H + f * PLANEF + slot * HSTRIDE + c0) =
                    make_float4(acc[f][0], acc[f][1], acc[f][2], acc[f][3]);
            }
        }
        __syncthreads();

        // -------- Stage B: vertical blur + ssim, 4 rows per thread ---------
        {
            const int c  = tid & (TX - 1);        // output column 0..63
            const int g4 = (tid >> 6) * 4;        // first output row in chunk
            const int b0 = y0c - 5 + g4;          // first tap's absolute row
            float v[5][4];
            #pragma unroll
            for (int f = 0; f < 5; f++)
                #pragma unroll
                for (int i = 0; i < 4; i++) v[f][i] = 0.f;

            #pragma unroll
            for (int k = 0; k < 14; k++) {
                const int off = ((b0 + k) & (HROWS - 1)) * HSTRIDE + c;
                float h[5];
                #pragma unroll
                for (int f = 0; f < 5; f++)
                    h[f] = H[f * PLANEF + off];
                #pragma unroll
                for (int jj = 0; jj < 4; jj++) {
                    const int t = k - jj;
                    if (t >= 0 && t <= 10) {
                        const float w = Wt(t);
                        #pragma unroll
                        for (int f = 0; f < 5; f++) v[f][jj] += w * h[f];
                    }
                }
            }

            // ssim fractions; combine 4 rationally -> ONE divide per chunk.
            float Nn[4], Dd[4];
            #pragma unroll
            for (int jj = 0; jj < 4; jj++) {
                const float mu1 = v[0][jj];
                const float mu2 = v[1][jj];
                const float mu12 = mu1 * mu2;
                const float mu1s = mu1 * mu1;
                const float mu2s = mu2 * mu2;
                const float s1  = v[2][jj] - mu1s;
                const float s2  = v[3][jj] - mu2s;
                const float s12 = v[4][jj] - mu12;
                Nn[jj] = (2.f * mu12 + C1f) * (2.f * s12 + C2f);
                Dd[jj] = (mu1s + mu2s + C1f) * (s1 + s2 + C2f);
            }
            const float n01 = Nn[0] * Dd[1] + Nn[1] * Dd[0];
            const float d01 = Dd[0] * Dd[1];
            const float n23 = Nn[2] * Dd[3] + Nn[3] * Dd[2];
            const float d23 = Dd[2] * Dd[3];
            lsum += __fdividef(n01 * d23 + n23 * d01, d01 * d23);
        }
    }

    // -------- Reduction ----------------------------------------------------
    #pragma unroll
    for (int o = 16; o > 0; o >>= 1)
        lsum += __shfl_xor_sync(0xffffffffu, lsum, o);
    if ((tid & 31) == 0) wsum[tid >> 5] = lsum;
    __syncthreads();
    if (tid == 0) {
        float bs = 0.f;
        #pragma unroll
        for (int w = 0; w < 8; w++) bs += wsum[w];
        atomicAdd(&g_acc, (double)bs);
        __threadfence();
        const unsigned old = atomicAdd(&g_count, 1u);
        if (old == NBLOCKS - 1) {
            const double s = *((volatile double*)&g_acc);
            out[0] = (float)(1.0 - s * (1.0 / 33554432.0));  // 32*1024*1024
            *((volatile double*)&g_acc) = 0.0;
            __threadfence();
            atomicExch(&g_count, 0u);
        }
    }
}

extern "C" void kernel_launch(void* const* d_in, const int* in_sizes, int n_in,
                              void* d_out, int out_size) {
    (void)in_sizes; (void)n_in; (void)out_size;
    const float* img1 = (const float*)d_in[0];
    const float* img2 = (const float*)d_in[1];
    float* out = (float*)d_out;

    static int smem_set = 0;
    if (!smem_set) {
        cudaFuncSetAttribute(ssim_main,
                             cudaFuncAttributeMaxDynamicSharedMemorySize,
                             SMEM_BYTES);
        smem_set = 1;
    }

    dim3 grid(IMG / TX, IMG / SY, 32);   // 16 x 8 x 32 = 4096 blocks
    ssim_main<<<grid, NTHREADS, SMEM_BYTES>>>(img1, img2, out);
}

// round 14
// speedup vs baseline: 1.1755x; 1.0200x over previous
#include <cuda_runtime.h>

// ---------------------------------------------------------------------------
// SSIM loss, fused strip kernel, ring-buffered horizontal-blur planes,
// gmem-direct stage A, 5 blocks/SM, power-of-2 ring addressing.
// Block owns a 64 (x) x 256 (y) strip, processed as 16 chunks of 16 rows.
// H: 5 scalar planes [32][64] used as a 32-row ring keyed by (gy & 31);
//    HSTRIDE=64 -> ring offsets are shifts, not IMADs.
// Stage A: horizontal 11-tap blur of 5 moment fields, 4-col register runs,
//          inputs read directly from gmem as aligned float4 (interior
//          blocks; 2/16 x-edge blocks take a predicated scalar path).
// Stage B: vertical 11-tap blur + ssim epilogue, 4-row runs; 4 fractions
//          combine rationally -> ONE __fdividef per chunk.
// Weights are compile-time immediates -> FFMA-imm (rt_SMSP=1).
// Reduce: warp shuffle -> block -> atomicAdd(double); counter-elected last
//         block writes 1 - mean and resets accumulators (replay-safe).
// ---------------------------------------------------------------------------

#define NTHREADS 256
#define TX 64
#define TY 16            // rows per chunk
#define NCHUNK 16        // chunks per strip
#define SY (TY * NCHUNK) // 256 rows per strip
#define HROWS 32         // ring rows (power of 2)
#define HSTRIDE 64       // H row stride (floats), power of 2
#define IMG 1024
#define NBLOCKS (16 * 4 * 32)

#define PLANEF (HROWS * HSTRIDE)
#define SMEM_FLOATS (5 * PLANEF + 8)
#define SMEM_BYTES (SMEM_FLOATS * 4)     // 40,992 B -> 5 blocks/SM

static __device__ __forceinline__ float Wt(int t) {
    // Gaussian, WIN=11, SIGMA=1.5, normalized; compile-time constants so
    // ptxas emits FFMA-imm (rt_SMSP=1, 2x tput vs 3-reg FFMA).
    constexpr float w[6] = {0.00102838f, 0.00759875f, 0.03600077f,
                            0.10936069f, 0.21300553f, 0.26601172f};
    return (t < 6) ? w[t] : w[10 - t];
}

__device__ double g_acc = 0.0;
__device__ unsigned g_count = 0u;

__global__ __launch_bounds__(NTHREADS, 5)
void ssim_main(const float* __restrict__ img1, const float* __restrict__ img2,
               float* __restrict__ out) {
    extern __shared__ float smem[];
    float* H    = smem;                 // [5][HROWS][HSTRIDE] ring
    float* wsum = smem + 5 * PLANEF;    // [8]

    const float C1f = 0.0004f;   // (0.01*2)^2
    const float C2f = 0.0036f;   // (0.03*2)^2

    const int tid = threadIdx.x;
    const int tx0 = blockIdx.x * TX;
    const int sy0 = blockIdx.y * SY;
    const size_t base = (size_t)blockIdx.z * (size_t)(IMG * IMG);
    const bool xedge = (blockIdx.x == 0) | (blockIdx.x == (IMG / TX - 1));

    float lsum = 0.f;

    #pragma unroll 1
    for (int ch = 0; ch < NCHUNK; ch++) {
        const int y0c = sy0 + ch * TY;   // first output row of this chunk

        if (ch > 0) __syncthreads();     // stage B readers done before slot reuse

        // -------- Stage A: horizontal blur of new rows into ring ------------
        // chunk 0: 26 rows (gy in [y0c-5, y0c+21)), 416 jobs (2 passes);
        // steady : 16 rows (gy in [y0c+5, y0c+21)), 256 jobs (1 pass).
        const int nrows  = (ch == 0) ? 26 : TY;
        const int row_lo = (ch == 0) ? -5 : 5;
        for (int j = tid; j < nrows * 16; j += NTHREADS) {
            const int r  = j >> 4;
            const int c0 = (j & 15) * 4;            // output cols c0..c0+3
            const int gy = y0c + row_lo + r;
            const int slot = gy & (HROWS - 1);

            float acc[5][4];
            #pragma unroll
            for (int f = 0; f < 5; f++)
                #pragma unroll
                for (int i = 0; i < 4; i++) acc[f][i] = 0.f;

            if ((unsigned)gy < (unsigned)IMG) {
                const size_t rowo = base + (size_t)gy * IMG;
                const int gx0 = tx0 - 8 + c0;       // window start (aligned 4)
                if (!xedge) {
                    #pragma unroll
                    for (int q = 0; q < 5; q++) {
                        const float4 v1 = *reinterpret_cast<const float4*>(
                            img1 + rowo + gx0 + 4 * q);
                        const float4 v2 = *reinterpret_cast<const float4*>(
                            img2 + rowo + gx0 + 4 * q);
                        const float a4[4] = {v1.x, v1.y, v1.z, v1.w};
                        const float b4[4] = {v2.x, v2.y, v2.z, v2.w};
                        #pragma unroll
                        for (int i = 0; i < 4; i++) {
                            const int k = 4 * q + i - 3;   // tap window index
                            if (k >= 0 && k < 14) {
                                const float a = a4[i];
                                const float b = b4[i];
                                const float aa = a * a;
                                const float bb = b * b;
                                const float ab = a * b;
                                #pragma unroll
                                for (int jj = 0; jj < 4; jj++) {
                                    const int t = k - jj;
                                    if (t >= 0 && t <= 10) {
                                        const float w = Wt(t);
                                        acc[0][jj] += w * a;
                                        acc[1][jj] += w * b;
                                        acc[2][jj] += w * aa;
                                        acc[3][jj] += w * bb;
                                        acc[4][jj] += w * ab;
                                    }
                                }
                            }
                        }
                    }
                } else {
                    // edge blocks: predicated scalar loads (2/16 of grid.x)
                    #pragma unroll
                    for (int q = 0; q < 5; q++) {
                        #pragma unroll
                        for (int i = 0; i < 4; i++) {
                            const int k = 4 * q + i - 3;
                            if (k >= 0 && k < 14) {
                                const int gx = gx0 + 4 * q + i;
                                float a = 0.f, b = 0.f;
                                if ((unsigned)gx < (unsigned)IMG) {
                                    a = __ldg(img1 + rowo + gx);
                                    b = __ldg(img2 + rowo + gx);
                                }
                                const float aa = a * a;
                                const float bb = b * b;
                                const float ab = a * b;
                                #pragma unroll
                                for (int jj = 0; jj < 4; jj++) {
                                    const int t = k - jj;
                                    if (t >= 0 && t <= 10) {
                                        const float w = Wt(t);
                                        acc[0][jj] += w * a;
                                        acc[1][jj] += w * b;
                                        acc[2][jj] += w * aa;
                                        acc[3][jj] += w * bb;
                                        acc[4][jj] += w * ab;
                                    }
                                }
                            }
                        }
                    }
                }
            }
            const int so = (slot << 6) + c0;   // slot * HSTRIDE + c0
            float* hp = H + so;
            #pragma unroll
            for (int f = 0; f < 5; f++) {
                *reinterpret_cast<float4*>(hp) =
                    make_float4(acc[f][0], acc[f][1], acc[f][2], acc[f][3]);
                hp += PLANEF;
            }
        }
        __syncthreads();

        // -------- Stage B: vertical blur + ssim, 4 rows per thread ---------
        {
            const int c  = tid & (TX - 1);        // output column 0..63
            const int g4 = (tid >> 6) * 4;        // first output row in chunk
            const int b0 = y0c - 5 + g4;          // first tap's absolute row
            const float* hb = H + c;
            float v[5][4];
            #pragma unroll
            for (int f = 0; f < 5; f++)
                #pragma unroll
                for (int i = 0; i < 4; i++) v[f][i] = 0.f;

            #pragma unroll
            for (int k = 0; k < 14; k++) {
                const int off = ((b0 + k) & (HROWS - 1)) << 6;  // * HSTRIDE
                const float* hk = hb + off;
                float h[5];
                #pragma unroll
                for (int f = 0; f < 5; f++) {
                    h[f] = *hk;
                    hk += PLANEF;
                }
                #pragma unroll
                for (int jj = 0; jj < 4; jj++) {
                    const int t = k - jj;
                    if (t >= 0 && t <= 10) {
                        const float w = Wt(t);
                        #pragma unroll
                        for (int f = 0; f < 5; f++) v[f][jj] += w * h[f];
                    }
                }
            }

            // ssim fractions; combine 4 rationally -> ONE divide per chunk.
            float Nn[4], Dd[4];
            #pragma unroll
            for (int jj = 0; jj < 4; jj++) {
                const float mu1 = v[0][jj];
                const float mu2 = v[1][jj];
                const float mu12 = mu1 * mu2;
                const float mu1s = mu1 * mu1;
                const float mu2s = mu2 * mu2;
                const float s1  = v[2][jj] - mu1s;
                const float s2  = v[3][jj] - mu2s;
                const float s12 = v[4][jj] - mu12;
                Nn[jj] = (2.f * mu12 + C1f) * (2.f * s12 + C2f);
                Dd[jj] = (mu1s + mu2s + C1f) * (s1 + s2 + C2f);
            }
            const float n01 = Nn[0] * Dd[1] + Nn[1] * Dd[0];
            const float d01 = Dd[0] * Dd[1];
            const float n23 = Nn[2] * Dd[3] + Nn[3] * Dd[2];
            const float d23 = Dd[2] * Dd[3];
            lsum += __fdividef(n01 * d23 + n23 * d01, d01 * d23);
        }
    }

    // -------- Reduction ----------------------------------------------------
    #pragma unroll
    for (int o = 16; o > 0; o >>= 1)
        lsum += __shfl_xor_sync(0xffffffffu, lsum, o);
    if ((tid & 31) == 0) wsum[tid >> 5] = lsum;
    __syncthreads();
    if (tid == 0) {
        float bs = 0.f;
        #pragma unroll
        for (int w = 0; w < 8; w++) bs += wsum[w];
        atomicAdd(&g_acc, (double)bs);
        __threadfence();
        const unsigned old = atomicAdd(&g_count, 1u);
        if (old == NBLOCKS - 1) {
            const double s = *((volatile double*)&g_acc);
            out[0] = (float)(1.0 - s * (1.0 / 33554432.0));  // 32*1024*1024
            *((volatile double*)&g_acc) = 0.0;
            __threadfence();
            atomicExch(&g_count, 0u);
        }
    }
}

extern "C" void kernel_launch(void* const* d_in, const int* in_sizes, int n_in,
                              void* d_out, int out_size) {
    (void)in_sizes; (void)n_in; (void)out_size;
    const float* img1 = (const float*)d_in[0];
    const float* img2 = (const float*)d_in[1];
    float* out = (float*)d_out;

    static int smem_set = 0;
    if (!smem_set) {
        cudaFuncSetAttribute(ssim_main,
                             cudaFuncAttributeMaxDynamicSharedMemorySize,
                             SMEM_BYTES);
        smem_set = 1;
    }

    dim3 grid(IMG / TX, IMG / SY, 32);   // 16 x 4 x 32 = 2048 blocks
    ssim_main<<<grid, NTHREADS, SMEM_BYTES>>>(img1, img2, out);
}

// round 15
// speedup vs baseline: 1.3434x; 1.1428x over previous
#include <cuda_runtime.h>

// ---------------------------------------------------------------------------
// SSIM loss, fused strip kernel, ring-buffered horizontal-blur planes,
// gmem-direct stage A, 5 blocks/SM, 4-field algebraic reduction.
// Key identity: denominator needs only blur(a^2)+blur(b^2), numerator only
// blur(ab).  With P = blur((a+b)^2), M = blur((a-b)^2):
//   blur(a^2+b^2) = (P+M)/2,  blur(ab) = (P-M)/4.
// So we blur 4 fields {a, b, (a+b)^2, (a-b)^2} instead of 5 -> 20% less
// blur work in BOTH stages, 4 H planes instead of 5.
// Block owns a 64 (x) x 256 (y) strip, processed as 16 chunks of 16 rows.
// H: 4 scalar planes [32][64] ring keyed by (gy & 31); HSTRIDE=64 (shifts).
// Stage A: horizontal 11-tap blur, 4-col register runs, gmem float4 direct.
// Stage B: vertical 11-tap blur + ssim epilogue, 4-row runs; 4 fractions
//          combine rationally -> ONE __fdividef per chunk.
// Reduce: warp shuffle -> block -> atomicAdd(double); counter-elected last
//         block writes 1 - mean and resets accumulators (replay-safe).
// ---------------------------------------------------------------------------

#define NTHREADS 256
#define TX 64
#define TY 16            // rows per chunk
#define NCHUNK 16        // chunks per strip
#define SY (TY * NCHUNK) // 256 rows per strip
#define HROWS 32         // ring rows (power of 2)
#define HSTRIDE 64       // H row stride (floats), power of 2
#define IMG 1024
#define NBLOCKS (16 * 4 * 32)

#define PLANEF (HROWS * HSTRIDE)
#define SMEM_FLOATS (4 * PLANEF + 8)
#define SMEM_BYTES (SMEM_FLOATS * 4)     // 32,800 B -> 5 blocks/SM

static __device__ __forceinline__ float Wt(int t) {
    // Gaussian, WIN=11, SIGMA=1.5, normalized; compile-time constants so
    // ptxas emits FFMA-imm (rt_SMSP=1, 2x tput vs 3-reg FFMA).
    constexpr float w[6] = {0.00102838f, 0.00759875f, 0.03600077f,
                            0.10936069f, 0.21300553f, 0.26601172f};
    return (t < 6) ? w[t] : w[10 - t];
}

__device__ double g_acc = 0.0;
__device__ unsigned g_count = 0u;

__global__ __launch_bounds__(NTHREADS, 5)
void ssim_main(const float* __restrict__ img1, const float* __restrict__ img2,
               float* __restrict__ out) {
    extern __shared__ float smem[];
    float* H    = smem;                 // [4][HROWS][HSTRIDE] ring
    float* wsum = smem + 4 * PLANEF;    // [8]

    const float C1f = 0.0004f;   // (0.01*2)^2
    const float C2f = 0.0036f;   // (0.03*2)^2

    const int tid = threadIdx.x;
    const int tx0 = blockIdx.x * TX;
    const int sy0 = blockIdx.y * SY;
    const size_t base = (size_t)blockIdx.z * (size_t)(IMG * IMG);
    const bool xedge = (blockIdx.x == 0) | (blockIdx.x == (IMG / TX - 1));

    float lsum = 0.f;

    #pragma unroll 1
    for (int ch = 0; ch < NCHUNK; ch++) {
        const int y0c = sy0 + ch * TY;   // first output row of this chunk

        if (ch > 0) __syncthreads();     // stage B readers done before slot reuse

        // -------- Stage A: horizontal blur of new rows into ring ------------
        // chunk 0: 26 rows (gy in [y0c-5, y0c+21)), 416 jobs (2 passes);
        // steady : 16 rows (gy in [y0c+5, y0c+21)), 256 jobs (1 pass).
        const int nrows  = (ch == 0) ? 26 : TY;
        const int row_lo = (ch == 0) ? -5 : 5;
        for (int j = tid; j < nrows * 16; j += NTHREADS) {
            const int r  = j >> 4;
            const int c0 = (j & 15) * 4;            // output cols c0..c0+3
            const int gy = y0c + row_lo + r;
            const int slot = gy & (HROWS - 1);

            float acc[4][4];
            #pragma unroll
            for (int f = 0; f < 4; f++)
                #pragma unroll
                for (int i = 0; i < 4; i++) acc[f][i] = 0.f;

            if ((unsigned)gy < (unsigned)IMG) {
                const size_t rowo = base + (size_t)gy * IMG;
                const int gx0 = tx0 - 8 + c0;       // window start (aligned 4)
                if (!xedge) {
                    #pragma unroll
                    for (int q = 0; q < 5; q++) {
                        const float4 v1 = *reinterpret_cast<const float4*>(
                            img1 + rowo + gx0 + 4 * q);
                        const float4 v2 = *reinterpret_cast<const float4*>(
                            img2 + rowo + gx0 + 4 * q);
                        const float a4[4] = {v1.x, v1.y, v1.z, v1.w};
                        const float b4[4] = {v2.x, v2.y, v2.z, v2.w};
                        #pragma unroll
                        for (int i = 0; i < 4; i++) {
                            const int k = 4 * q + i - 3;   // tap window index
                            if (k >= 0 && k < 14) {
                                const float a = a4[i];
                                const float b = b4[i];
                                const float p = a + b;
                                const float m = a - b;
                                const float pp = p * p;
                                const float mm = m * m;
                                #pragma unroll
                                for (int jj = 0; jj < 4; jj++) {
                                    const int t = k - jj;
                                    if (t >= 0 && t <= 10) {
                                        const float w = Wt(t);
                                        acc[0][jj] += w * a;
                                        acc[1][jj] += w * b;
                                        acc[2][jj] += w * pp;
                                        acc[3][jj] += w * mm;
                                    }
                                }
                            }
                        }
                    }
                } else {
                    // edge blocks: predicated scalar loads (2/16 of grid.x)
                    #pragma unroll
                    for (int q = 0; q < 5; q++) {
                        #pragma unroll
                        for (int i = 0; i < 4; i++) {
                            const int k = 4 * q + i - 3;
                            if (k >= 0 && k < 14) {
                                const int gx = gx0 + 4 * q + i;
                                float a = 0.f, b = 0.f;
                                if ((unsigned)gx < (unsigned)IMG) {
                                    a = __ldg(img1 + rowo + gx);
                                    b = __ldg(img2 + rowo + gx);
                                }
                                const float p = a + b;
                                const float m = a - b;
                                const float pp = p * p;
                                const float mm = m * m;
                                #pragma unroll
                                for (int jj = 0; jj < 4; jj++) {
                                    const int t = k - jj;
                                    if (t >= 0 && t <= 10) {
                                        const float w = Wt(t);
                                        acc[0][jj] += w * a;
                                        acc[1][jj] += w * b;
                                        acc[2][jj] += w * pp;
                                        acc[3][jj] += w * mm;
                                    }
                                }
                            }
                        }
                    }
                }
            }
            const int so = (slot << 6) + c0;   // slot * HSTRIDE + c0
            float* hp = H + so;
            #pragma unroll
            for (int f = 0; f < 4; f++) {
                *reinterpret_cast<float4*>(hp) =
                    make_float4(acc[f][0], acc[f][1], acc[f][2], acc[f][3]);
                hp += PLANEF;
            }
        }
        __syncthreads();

        // -------- Stage B: vertical blur + ssim, 4 rows per thread ---------
        {
            const int c  = tid & (TX - 1);        // output column 0..63
            const int g4 = (tid >> 6) * 4;        // first output row in chunk
            const int b0 = y0c - 5 + g4;          // first tap's absolute row
            const float* hb = H + c;
            float v[4][4];
            #pragma unroll
            for (int f = 0; f < 4; f++)
                #pragma unroll
                for (int i = 0; i < 4; i++) v[f][i] = 0.f;

            #pragma unroll
            for (int k = 0; k < 14; k++) {
                const int off = ((b0 + k) & (HROWS - 1)) << 6;  // * HSTRIDE
                const float* hk = hb + off;
                float h[4];
                #pragma unroll
                for (int f = 0; f < 4; f++) {
                    h[f] = *hk;
                    hk += PLANEF;
                }
                #pragma unroll
                for (int jj = 0; jj < 4; jj++) {
                    const int t = k - jj;
                    if (t >= 0 && t <= 10) {
                        const float w = Wt(t);
                        #pragma unroll
                        for (int f = 0; f < 4; f++) v[f][jj] += w * h[f];
                    }
                }
            }

            // ssim fractions from 4 fields; combine rationally -> ONE divide.
            float Nn[4], Dd[4];
            #pragma unroll
            for (int jj = 0; jj < 4; jj++) {
                const float mu1 = v[0][jj];
                const float mu2 = v[1][jj];
                const float P   = v[2][jj];       // blur((a+b)^2)
                const float M   = v[3][jj];       // blur((a-b)^2)
                const float mu12 = mu1 * mu2;
                const float mu1s = mu1 * mu1;
                const float mu2s = mu2 * mu2;
                const float sumsq = 0.5f * (P + M);    // blur(a^2)+blur(b^2)
                const float abv   = 0.25f * (P - M);   // blur(ab)
                const float s12   = abv - mu12;
                const float musum = mu1s + mu2s;
                Nn[jj] = (2.f * mu12 + C1f) * (2.f * s12 + C2f);
                Dd[jj] = (musum + C1f) * (sumsq - musum + C2f);
            }
            const float n01 = Nn[0] * Dd[1] + Nn[1] * Dd[0];
            const float d01 = Dd[0] * Dd[1];
            const float n23 = Nn[2] * Dd[3] + Nn[3] * Dd[2];
            const float d23 = Dd[2] * Dd[3];
            lsum += __fdividef(n01 * d23 + n23 * d01, d01 * d23);
        }
    }

    // -------- Reduction ----------------------------------------------------
    #pragma unroll
    for (int o = 16; o > 0; o >>= 1)
        lsum += __shfl_xor_sync(0xffffffffu, lsum, o);
    if ((tid & 31) == 0) wsum[tid >> 5] = lsum;
    __syncthreads();
    if (tid == 0) {
        float bs = 0.f;
        #pragma unroll
        for (int w = 0; w < 8; w++) bs += wsum[w];
        atomicAdd(&g_acc, (double)bs);
        __threadfence();
        const unsigned old = atomicAdd(&g_count, 1u);
        if (old == NBLOCKS - 1) {
            const double s = *((volatile double*)&g_acc);
            out[0] = (float)(1.0 - s * (1.0 / 33554432.0));  // 32*1024*1024
            *((volatile double*)&g_acc) = 0.0;
            __threadfence();
            atomicExch(&g_count, 0u);
        }
    }
}

extern "C" void kernel_launch(void* const* d_in, const int* in_sizes, int n_in,
                              void* d_out, int out_size) {
    (void)in_sizes; (void)n_in; (void)out_size;
    const float* img1 = (const float*)d_in[0];
    const float* img2 = (const float*)d_in[1];
    float* out = (float*)d_out;

    static int smem_set = 0;
    if (!smem_set) {
        cudaFuncSetAttribute(ssim_main,
                             cudaFuncAttributeMaxDynamicSharedMemorySize,
                             SMEM_BYTES);
        smem_set = 1;
    }

    dim3 grid(IMG / TX, IMG / SY, 32);   // 16 x 4 x 32 = 2048 blocks
    ssim_main<<<grid, NTHREADS, SMEM_BYTES>>>(img1, img2, out);
}